// round 7
// baseline (speedup 1.0000x reference)
#include <cuda_runtime.h>
#include <cuda_bf16.h>

#define OUT_CH  128
#define EPB     8            // edges per block
#define THREADS 256
#define NW      (THREADS/32) // 8 warps

// Single fused kernel. Block b owns edges [b*EPB, (b+1)*EPB).
//  - 8 warps find all 9 edge boundaries via windowed warp-parallel lower_bound
//    (guess = target*T/E, verified window, geometric expansion => correct for
//     any sorted input; ~3 ballot rounds on uniform data)
//  - all threads stream ONLY the tokens array (coalesced, 32B/lane), mapping
//    each token to its edge by walking the register-held boundary list;
//    packed-u64 register accumulator, flushed to private conflict-free smem
//    slots on edge change (no atomics anywhere)
//  - warp w reduces + writes edge e0+w's 128-channel mean row
__global__ void __launch_bounds__(THREADS)
fused_edge_mean(const int* __restrict__ tokens,
                const int* __restrict__ segs,
                const float* __restrict__ emb,   // [4][128]
                float* __restrict__ out,         // [E][128]
                int total_tokens,
                int n_edges) {
    __shared__ unsigned long long s_acc[NW][EPB][32];   // 16 KB, private slots
    __shared__ int s_bound[EPB + 1];

    const int tid  = threadIdx.x;
    const int lane = tid & 31;
    const int wid  = tid >> 5;
    const int e0   = blockIdx.x * EPB;

#pragma unroll
    for (int k = 0; k < EPB; k++) s_acc[wid][k][lane] = 0ull;

    // ---- 9 boundaries: warp w handles b = w (and warp 0 also b = 8) ----
    for (int b = wid; b <= EPB; b += NW) {
        const int target = e0 + b;

        // windowed guess around expected position, verified + expandable
        const long long g = (long long)target * total_tokens / n_edges;
        int W = 8192;
        int lo, hi;
        for (;;) {
            lo = (int)(g - W < 0 ? 0 : g - W);
            hi = (int)(g + W > total_tokens ? total_tokens : g + W);
            const bool ok_lo = (lo == 0) || (__ldg(&segs[lo - 1]) < target);
            const bool ok_hi = (hi >= total_tokens) || (__ldg(&segs[hi]) >= target);
            if (ok_lo && ok_hi) break;
            W <<= 3;
            if (W >= total_tokens) { lo = 0; hi = total_tokens; break; }
        }

        // warp-parallel 32-ary lower_bound on [lo, hi]
        while (hi > lo) {
            const int step = (hi - lo + 31) >> 5;
            const int idx  = lo + lane * step;
            int v = 0x7FFFFFFF;
            if (idx < hi) v = __ldg(&segs[idx]);
            const unsigned m = __ballot_sync(0xFFFFFFFFu, v < target);
            const int cnt = __popc(m);                 // sorted -> contiguous
            const int nlo = cnt ? lo + (cnt - 1) * step + 1 : lo;
            const int nhi = (cnt < 32) ? min(hi, lo + cnt * step) : hi;
            lo = nlo; hi = max(nhi, nlo);
        }
        if (lane == 0) s_bound[b] = lo;
    }
    __syncthreads();

    // boundary list into registers
    int rb[EPB + 1];
#pragma unroll
    for (int k = 0; k <= EPB; k++) rb[k] = s_bound[k];

    const int start = rb[0];
    const int end   = rb[EPB];

    // ---- stream tokens only: one 8-token chunk (2 x int4) per thread/iter ----
    const int4* tokens4 = (const int4*)tokens;
    const int p0 = start >> 3;          // 8-token chunk index
    const int p1 = (end + 7) >> 3;      // T is a multiple of 8

    // current edge slot for this thread's monotone token positions
    int le = -1;
    {
        const int idx0 = (p0 + tid) << 3;
#pragma unroll
        for (int k = 0; k <= EPB; k++) le += (rb[k] <= idx0);
    }
    int nextb = (le < 0) ? rb[0] : ((le < EPB) ? rb[le + 1] : 0x7FFFFFFF);

    unsigned long long acc = 0ull;      // count of token t in 16-bit field t

#define STEP(IDX, T)                                                        \
    do {                                                                    \
        if ((IDX) >= nextb) {            /* rare: crossed a boundary */     \
            if (acc && (unsigned)le < EPB) s_acc[wid][le][lane] += acc;     \
            acc = 0ull;                                                     \
            le++;                                                           \
            while (le < EPB && (IDX) >= rb[le + 1]) le++;                   \
            nextb = (le < EPB) ? rb[le + 1] : 0x7FFFFFFF;                   \
        }                                                                   \
        acc += 1ull << ((T) * 16);                                          \
    } while (0)

    for (int p = p0 + tid; p < p1; p += THREADS) {
        const int4 ta = tokens4[2 * p];
        const int4 tb = tokens4[2 * p + 1];
        const int base = p << 3;
        STEP(base + 0, ta.x); STEP(base + 1, ta.y);
        STEP(base + 2, ta.z); STEP(base + 3, ta.w);
        STEP(base + 4, tb.x); STEP(base + 5, tb.y);
        STEP(base + 6, tb.z); STEP(base + 7, tb.w);
    }
    if (acc && (unsigned)le < EPB) s_acc[wid][le][lane] += acc;
#undef STEP
    __syncthreads();

    // ---- epilogue: warp w reduces + writes edge e0+w ----
    const int e = e0 + wid;
    if (e < n_edges) {
        unsigned long long sum = 0ull;
#pragma unroll
        for (int w = 0; w < NW; w++) sum += s_acc[w][wid][lane];

        // per-field totals << 65536: halves reduce carry-free
        const unsigned lo32 = __reduce_add_sync(0xFFFFFFFFu, (unsigned)sum);
        const unsigned hi32 = __reduce_add_sync(0xFFFFFFFFu, (unsigned)(sum >> 32));

        const float f0 = (float)(lo32 & 0xFFFFu);
        const float f1 = (float)(lo32 >> 16);
        const float f2 = (float)(hi32 & 0xFFFFu);
        const float f3 = (float)(hi32 >> 16);
        const float inv = 1.0f / fmaxf(f0 + f1 + f2 + f3, 1.0f);

        const int d = lane * 4;
        const float4 e0v = *(const float4*)(emb + 0 * OUT_CH + d);
        const float4 e1v = *(const float4*)(emb + 1 * OUT_CH + d);
        const float4 e2v = *(const float4*)(emb + 2 * OUT_CH + d);
        const float4 e3v = *(const float4*)(emb + 3 * OUT_CH + d);

        float4 r;
        r.x = (f0 * e0v.x + f1 * e1v.x + f2 * e2v.x + f3 * e3v.x) * inv;
        r.y = (f0 * e0v.y + f1 * e1v.y + f2 * e2v.y + f3 * e3v.y) * inv;
        r.z = (f0 * e0v.z + f1 * e1v.z + f2 * e2v.z + f3 * e3v.z) * inv;
        r.w = (f0 * e0v.w + f1 * e1v.w + f2 * e2v.w + f3 * e3v.w) * inv;

        *(float4*)(out + (long long)e * OUT_CH + d) = r;
    }
}

extern "C" void kernel_launch(void* const* d_in, const int* in_sizes, int n_in,
                              void* d_out, int out_size) {
    // Inputs: 0 overlap_similarity f32[E], 1 overlap_length f32[E],
    //         2 tokens i32[T], 3 segment_ids i32[T], 4 embedding f32[4*128],
    //         5 n_edges
    const int*   tokens = (const int*)d_in[2];
    const int*   segs   = (const int*)d_in[3];
    const float* emb    = (const float*)d_in[4];
    float*       out    = (float*)d_out;

    const int total_tokens = in_sizes[2];
    const int n_edges      = out_size / OUT_CH;

    const int blocks = (n_edges + EPB - 1) / EPB;   // 1024
    fused_edge_mean<<<blocks, THREADS>>>(tokens, segs, emb, out,
                                         total_tokens, n_edges);
}

// round 8
// speedup vs baseline: 1.1225x; 1.1225x over previous
#include <cuda_runtime.h>
#include <cuda_bf16.h>

#define OUT_CH  128
#define EPB     8            // edges per block
#define THREADS 256
#define NW      (THREADS/32) // 8 warps

// Block b owns edges [b*EPB, (b+1)*EPB).
//  - 8 warps find the 9 edge boundaries via WINDOWED warp-parallel lower_bound
//    (guess = target*T/E, verified +-2048 window, geometric expansion: correct
//     for any sorted input, ~3 ballot rounds of near probes on uniform data)
//  - stream ONLY tokens (8 MB total): 8-token chunks, fast path = whole chunk
//    in current edge -> two 256-entry packed-u64 LUT lookups; boundary state
//    is two scalar registers, boundaries re-read from smem on crossings only
//  - accumulate into private conflict-free smem slots (no atomics anywhere)
//  - warp w reduces + writes edge e0+w's 128-channel mean row
__global__ void __launch_bounds__(THREADS)
fused_edge_mean(const int* __restrict__ tokens,
                const int* __restrict__ segs,
                const float* __restrict__ emb,   // [4][128]
                float* __restrict__ out,         // [E][128]
                int total_tokens,
                int n_edges) {
    __shared__ unsigned long long s_acc[NW][EPB][32];   // 16 KB private slots
    __shared__ unsigned long long s_lut[256];           // 2 KB packed counts
    __shared__ int s_bound[EPB + 1];

    const int tid  = threadIdx.x;
    const int lane = tid & 31;
    const int wid  = tid >> 5;
    const int e0   = blockIdx.x * EPB;

    // LUT: entry i = sum over the 4 packed 2-bit token values of (1 << t*16)
    {
        const int t0 = tid & 3, t1 = (tid >> 2) & 3,
                  t2 = (tid >> 4) & 3, t3 = (tid >> 6) & 3;
        s_lut[tid] = (1ull << (t0 * 16)) + (1ull << (t1 * 16))
                   + (1ull << (t2 * 16)) + (1ull << (t3 * 16));
    }
#pragma unroll
    for (int k = 0; k < EPB; k++) s_acc[wid][k][lane] = 0ull;

    // ---- boundaries: warp w -> b = w; warp 0 also b = 8 ----
    for (int b = wid; b <= EPB; b += NW) {
        const int target = e0 + b;
        const long long g = (long long)target * total_tokens / n_edges;
        int W = 2048;
        int lo, hi;
        for (;;) {
            lo = (int)(g - W < 0 ? 0 : g - W);
            hi = (int)(g + W > total_tokens ? total_tokens : g + W);
            const bool ok_lo = (lo == 0) || (__ldg(&segs[lo - 1]) < target);
            const bool ok_hi = (hi >= total_tokens) || (__ldg(&segs[hi]) >= target);
            if (ok_lo && ok_hi) break;
            W <<= 3;
            if (W >= total_tokens) { lo = 0; hi = total_tokens; break; }
        }
        while (hi > lo) {                     // warp-parallel 32-ary lower_bound
            const int step = (hi - lo + 31) >> 5;
            const int idx  = lo + lane * step;
            int v = 0x7FFFFFFF;
            if (idx < hi) v = __ldg(&segs[idx]);
            const unsigned m = __ballot_sync(0xFFFFFFFFu, v < target);
            const int cnt = __popc(m);        // sorted -> contiguous mask
            const int nlo = cnt ? lo + (cnt - 1) * step + 1 : lo;
            const int nhi = (cnt < 32) ? min(hi, lo + cnt * step) : hi;
            lo = nlo; hi = max(nhi, nlo);
        }
        if (lane == 0) s_bound[b] = lo;
    }
    __syncthreads();

    const int start = s_bound[0];
    const int end   = s_bound[EPB];

    // ---- stream tokens: 8-token chunks (2 x int4), tokens array only ----
    const int4* tokens4 = (const int4*)tokens;
    const int p0 = start >> 3;
    const int p1 = (end + 7) >> 3;           // T is a multiple of 8

    // le = current local edge (-1 = before our first edge, EPB = past last)
    int le = -1;
#pragma unroll
    for (int k = 0; k <= EPB; k++) le += (s_bound[k] <= ((p0 + tid) << 3));
    int nextb = (le < 0) ? s_bound[0] : ((le < EPB) ? s_bound[le + 1] : 0x7FFFFFFF);

    unsigned long long acc = 0ull;

#define FLUSH() do { if ((unsigned)le < EPB && acc) s_acc[wid][le][lane] += acc; \
                     acc = 0ull; } while (0)
#define ADVANCE(IDX) do {                                                     \
        FLUSH();                                                              \
        le++;                                                                 \
        while (le < EPB && (IDX) >= s_bound[le + 1]) le++;                    \
        nextb = (le < EPB) ? s_bound[le + 1] : 0x7FFFFFFF;                    \
    } while (0)

    for (int p = p0 + tid; p < p1; p += THREADS) {
        const int4 ta = tokens4[2 * p];
        const int4 tb = tokens4[2 * p + 1];
        const int base = p << 3;

        if (base + 8 <= nextb && base >= nextb - 0x7FFF0000) {
            // fast path: whole chunk inside current edge (le may be -1/EPB;
            // those contributions are dropped at flush). Second condition is
            // always true (keeps nextb semantics explicit, folds away).
            const int ia = (ta.x & 3) | ((ta.y & 3) << 2)
                         | ((ta.z & 3) << 4) | ((ta.w & 3) << 6);
            const int ib = (tb.x & 3) | ((tb.y & 3) << 2)
                         | ((tb.z & 3) << 4) | ((tb.w & 3) << 6);
            acc += s_lut[ia] + s_lut[ib];
        } else {
            const int tt[8] = {ta.x, ta.y, ta.z, ta.w, tb.x, tb.y, tb.z, tb.w};
#pragma unroll
            for (int k = 0; k < 8; k++) {
                const int idx = base + k;
                if (idx >= nextb) ADVANCE(idx);
                acc += 1ull << ((tt[k] & 3) * 16);
            }
        }
    }
    FLUSH();
#undef ADVANCE
#undef FLUSH
    __syncthreads();

    // ---- epilogue: warp w reduces + writes edge e0+w ----
    const int e = e0 + wid;
    if (e < n_edges) {
        unsigned long long sum = 0ull;
#pragma unroll
        for (int w = 0; w < NW; w++) sum += s_acc[w][wid][lane];

        // per-field totals << 65536: halves reduce carry-free
        const unsigned lo32 = __reduce_add_sync(0xFFFFFFFFu, (unsigned)sum);
        const unsigned hi32 = __reduce_add_sync(0xFFFFFFFFu, (unsigned)(sum >> 32));

        const float f0 = (float)(lo32 & 0xFFFFu);
        const float f1 = (float)(lo32 >> 16);
        const float f2 = (float)(hi32 & 0xFFFFu);
        const float f3 = (float)(hi32 >> 16);
        const float inv = 1.0f / fmaxf(f0 + f1 + f2 + f3, 1.0f);

        const int d = lane * 4;
        const float4 e0v = *(const float4*)(emb + 0 * OUT_CH + d);
        const float4 e1v = *(const float4*)(emb + 1 * OUT_CH + d);
        const float4 e2v = *(const float4*)(emb + 2 * OUT_CH + d);
        const float4 e3v = *(const float4*)(emb + 3 * OUT_CH + d);

        float4 r;
        r.x = (f0 * e0v.x + f1 * e1v.x + f2 * e2v.x + f3 * e3v.x) * inv;
        r.y = (f0 * e0v.y + f1 * e1v.y + f2 * e2v.y + f3 * e3v.y) * inv;
        r.z = (f0 * e0v.z + f1 * e1v.z + f2 * e2v.z + f3 * e3v.z) * inv;
        r.w = (f0 * e0v.w + f1 * e1v.w + f2 * e2v.w + f3 * e3v.w) * inv;

        *(float4*)(out + (long long)e * OUT_CH + d) = r;
    }
}

extern "C" void kernel_launch(void* const* d_in, const int* in_sizes, int n_in,
                              void* d_out, int out_size) {
    // Inputs: 0 overlap_similarity f32[E], 1 overlap_length f32[E],
    //         2 tokens i32[T], 3 segment_ids i32[T], 4 embedding f32[4*128],
    //         5 n_edges
    const int*   tokens = (const int*)d_in[2];
    const int*   segs   = (const int*)d_in[3];
    const float* emb    = (const float*)d_in[4];
    float*       out    = (float*)d_out;

    const int total_tokens = in_sizes[2];
    const int n_edges      = out_size / OUT_CH;

    const int blocks = (n_edges + EPB - 1) / EPB;   // 1024
    fused_edge_mean<<<blocks, THREADS>>>(tokens, segs, emb, out,
                                         total_tokens, n_edges);
}